// round 12
// baseline (speedup 1.0000x reference)
#include <cuda_runtime.h>
#include <cuda_fp16.h>
#include <cstdint>

// ---------------- problem constants ----------------
#define BATCH   4
#define CIN     64
#define HH      192
#define WW      192
#define HW      36864
#define NPOLY   128
#define PPTS    128
#define FPK     8256
#define NSPLIT  12

// output layout (floats)
#define O_INIT   0
#define O_COARSE 32768
#define O_MBI    65536
#define O_MBC    (65536 + 4718592)
#define O_FEAT   (65536 + 2*4718592)

// conv A-slab geometry (32x4 pixel patch, 1-px halo)
#define SLAB_W  34
#define SLAB_PX 204
#define SLAB_ZERO 204
#define SLAB_BYTES 26240u      // 205 rows * 128 B
#define B_OFF   52480u         // 2 * SLAB_BYTES
#define B_STAGE 32768u
#define CONV_SMEM (52480 + 3*32768)   // 150784

// ---------------- device scratch ----------------
__device__ __half g_w1h[256 * 576];
__device__ __half g_w1l[256 * 576];
__device__ __half g_w2h[64 * 256];
__device__ __half g_w2l[64 * 256];
__device__ float  g_feat[BATCH * HW * CIN];
__device__ float  g_union[BATCH * HW];
__device__ float  g_init[NPOLY * PPTS * 2];
__device__ float  g_coarse[NPOLY * PPTS * 2];
__device__ float  g_fp[NPOLY * FPK];
__device__ float  g_tmp[NPOLY * 512];
__device__ float  g_part[NSPLIT * NPOLY * 512];

// ---------------- helpers ----------------
__device__ __forceinline__ uint32_t smem_u32(const void* p) {
    uint32_t a;
    asm("{ .reg .u64 t; cvta.to.shared.u64 t, %1; cvt.u32.u64 %0, t; }" : "=r"(a) : "l"(p));
    return a;
}
__device__ __forceinline__ void cp16(uint32_t dst, const void* src, int sz) {
    asm volatile("cp.async.ca.shared.global [%0], [%1], 16, %2;" :: "r"(dst), "l"(src), "r"(sz));
}
#define CP_COMMIT() asm volatile("cp.async.commit_group;")
#define CP_WAIT1()  asm volatile("cp.async.wait_group 1;")
#define CP_WAIT0()  asm volatile("cp.async.wait_group 0;")
__device__ __forceinline__ void ldmx4(uint32_t addr, uint32_t* r) {
    asm volatile("ldmatrix.sync.aligned.m8n8.x4.shared.b16 {%0,%1,%2,%3}, [%4];"
        : "=r"(r[0]), "=r"(r[1]), "=r"(r[2]), "=r"(r[3]) : "r"(addr));
}
__device__ __forceinline__ void hmma(float* d, const uint32_t* a, const uint32_t* b) {
    asm volatile("mma.sync.aligned.m16n8k16.row.col.f32.f16.f16.f32 "
        "{%0,%1,%2,%3}, {%4,%5,%6,%7}, {%8,%9}, {%0,%1,%2,%3};"
        : "+f"(d[0]), "+f"(d[1]), "+f"(d[2]), "+f"(d[3])
        : "r"(a[0]), "r"(a[1]), "r"(a[2]), "r"(a[3]), "r"(b[0]), "r"(b[1]));
}
__device__ __forceinline__ uint32_t swz64(int row, int colb) {
    return (uint32_t)(row * 64 + (colb ^ (((row >> 1) & 3) << 4)));
}
__device__ __forceinline__ uint32_t swz128(int row, int colb) {
    return (uint32_t)(row * 128 + (colb ^ ((row & 7) << 4)));
}
__device__ __forceinline__ void split_store(__half* hp, __half* lp, float v) {
    __half h = __float2half_rn(v);
    *hp = h;
    *lp = __float2half_rn(v - __half2float(h));
}

// ---------------- zero kernel: union + mb slack slots ----------------
__global__ void k_zero(const int* __restrict__ ct_num, float* __restrict__ mb) {
    int i = blockIdx.x * 256 + threadIdx.x;
    ((unsigned*)g_union)[i] = 0u;
    int b = i / HW, px = i - b * HW;
    int cn = ct_num[b];
    for (int c = cn; c < 32; c++)
        mb[(size_t)(b * 32 + c) * HW + px] = 0.0f;
}

// ---------------- pnp body ----------------
__device__ void pnp_body(int poly, int rg, int src,
                         const float* __restrict__ wh, const int* __restrict__ ct_ind,
                         const int* __restrict__ ct_img, const int* __restrict__ ct_num,
                         float* __restrict__ mb) {
    __shared__ float verts[256];
    __shared__ float xint[8][132];
    __shared__ int cnt[8];
    __shared__ int slots[4];
    int tid = threadIdx.x;
    int rb = rg * 8;

    if (src == 0) {
        int ind = ct_ind[poly];
        int img = ct_img[poly];
        int cx = ind % WW;
        int cy = ind / WW;
        int p = tid >> 1;
        size_t base = (size_t)img * 256 * HW + (size_t)cy * WW + cx;
        float off = wh[base + (size_t)(2 * p + (tid & 1)) * HW];
        verts[tid] = off * 10.0f + (float)((tid & 1) ? cy : cx);
    } else {
        verts[tid] = g_coarse[poly * 256 + tid];
    }
    if (tid < 8) cnt[tid] = 0;
    if (tid < 4) {
        int cnb = ct_num[tid];
        int start = (tid == 0) ? 0 : ct_num[tid - 1];   // reference slicing quirk
        int c = poly - start;
        slots[tid] = (c >= 0 && c < cnb) ? c : -1;
    }
    __syncthreads();
    for (int i = tid; i < 1024; i += 256) {
        int e = i & 127, r = i >> 7;
        float yy = (float)(rb + r);
        int e2 = (e + 1) & 127;
        float y1 = verts[2 * e + 1];
        float y2 = verts[2 * e2 + 1];
        if ((y1 > yy) != (y2 > yy)) {
            float x1 = verts[2 * e];
            float x2 = verts[2 * e2];
            float den = y2 - y1;
            if (fabsf(den) < 1e-9f) den = 1e-9f;
            float xi = x1 + (x2 - x1) * (yy - y1) / den;
            int s = atomicAdd(&cnt[r], 1);
            xint[r][s] = xi;
        }
    }
    __syncthreads();
    for (int i = tid; i < 1536; i += 256) {
        int r = i / 192;
        int xp = i - r * 192;
        int c = cnt[r];
        float fx = (float)xp;
        unsigned par = 0;
        for (int j = 0; j < c; j++) par ^= (fx < xint[r][j]) ? 1u : 0u;
        float parf = (float)par;
        int px = (rb + r) * WW + xp;
#pragma unroll
        for (int b = 0; b < 4; b++) {
            int sc = slots[b];
            if (sc >= 0) {
                mb[(size_t)(b * 32 + sc) * HW + px] = parf;
                if (par) atomicOr((unsigned*)&g_union[b * HW + px], 0x3F800000u);
            }
        }
    }
}

// ---------------- K0: init polys ----------------
__global__ void k_init(const float* __restrict__ wh, const int* __restrict__ ct_ind,
                       const int* __restrict__ ct_img, float* __restrict__ out_init) {
    int n = blockIdx.x;
    int p = threadIdx.x;
    int ind = ct_ind[n];
    int img = ct_img[n];
    int cx = ind % WW;
    int cy = ind / WW;
    size_t base = (size_t)img * 256 * HW + (size_t)cy * WW + cx;
    float ox = wh[base + (size_t)(2 * p) * HW];
    float oy = wh[base + (size_t)(2 * p + 1) * HW];
    float ix = ox * 10.0f + (float)cx;
    float iy = oy * 10.0f + (float)cy;
    int o = (n * PPTS + p) * 2;
    g_init[o + 0] = ix;
    g_init[o + 1] = iy;
    out_init[o + 0] = ix * 4.0f;
    out_init[o + 1] = iy * 4.0f;
}

// ---------------- front: weight split + pnp(init) (no transpose anymore) ----
__global__ __launch_bounds__(256) void k_front(const float* __restrict__ w1,
                                               const float* __restrict__ w2,
                                               const float* __restrict__ wh,
                                               const int* __restrict__ ct_ind,
                                               const int* __restrict__ ct_img,
                                               const int* __restrict__ ct_num,
                                               float* __restrict__ out_mbi) {
    int bid = blockIdx.x;
    if (bid < 640) {
        int i = bid * 256 + threadIdx.x;
        if (i < 147456) {
            int oc = i / 576, k = i - oc * 576;
            int tap = k >> 6, ic = k & 63;
            split_store(&g_w1h[i], &g_w1l[i], w1[(oc * 64 + ic) * 9 + tap]);
        } else {
            int j = i - 147456;
            split_store(&g_w2h[j], &g_w2l[j], w2[j]);
        }
        return;
    }
    int j = bid - 640;
    pnp_body(j % 64, j / 64, 0, wh, ct_ind, ct_img, ct_num, out_mbi);
}

// ---------------- pnp(coarse) ----------------
__global__ __launch_bounds__(256) void k_pnp_c(const int* __restrict__ ct_num,
                                               float* __restrict__ out_mbc) {
    pnp_body(blockIdx.y, blockIdx.x, 1, nullptr, nullptr, nullptr, ct_num, out_mbc);
}

// ---------------- fused conv1 + conv2 (+featmul) ----------------
// A slab loaded directly from NCHW fp32 input (split in-kernel, bit-identical).
__global__ __launch_bounds__(512, 1) void k_conv(const float* __restrict__ x,
                                                 const float* __restrict__ b1,
                                                 const float* __restrict__ b2) {
    extern __shared__ char sm[];
    uint32_t sb = smem_u32(sm);
    int tid = threadIdx.x, lane = tid & 31, wid = tid >> 5;
    int b = blockIdx.y;
    int px0 = (blockIdx.x % 6) * 32;
    int py0 = (blockIdx.x / 6) * 4;
    int wm = wid & 1, wn = wid >> 1;

    float acc[4][4][4];
#pragma unroll
    for (int i = 0; i < 4; i++)
#pragma unroll
        for (int j = 0; j < 4; j++)
#pragma unroll
            for (int k = 0; k < 4; k++) acc[i][j][k] = 0.0f;

    int ry[4], rx[4], sbs[4];
#pragma unroll
    for (int mt = 0; mt < 4; mt++) {
        int r = wm * 64 + mt * 16 + (lane & 15);
        int pr = r >> 5, pc = r & 31;
        ry[mt] = py0 + pr;
        rx[mt] = px0 + pc;
        sbs[mt] = (pr + 1) * SLAB_W + pc + 1;
    }

    int brow = tid >> 1;
    int bq0 = (tid & 1) * 2;
    const __half* w1h_p = g_w1h + (size_t)brow * 576 + bq0 * 8;
    const __half* w1l_p = g_w1l + (size_t)brow * 576 + bq0 * 8;
    uint32_t bd0 = swz64(brow, bq0 * 16);
    uint32_t bd1 = swz64(brow, bq0 * 16 + 16);

    auto load_b = [&](int chunk) {
        uint32_t st = sb + B_OFF + (uint32_t)(chunk % 3) * B_STAGE;
        int tap = chunk >> 1, half = chunk & 1;
        int wo = tap * 64 + half * 32;
        cp16(st + bd0, w1h_p + wo, 16);
        cp16(st + bd1, w1h_p + wo + 8, 16);
        cp16(st + 16384u + bd0, w1l_p + wo, 16);
        cp16(st + 16384u + bd1, w1l_p + wo + 8, 16);
    };

    // issue B prefetch first (async), then build A slab synchronously
    load_b(0); CP_COMMIT();
    load_b(1); CP_COMMIT();

    {
        const float* xb = x + (size_t)b * CIN * HW;
        // 208 pixel slots (205 used incl zero row) x 64 ch = 13312 = 26 * 512
#pragma unroll 2
        for (int it = 0; it < 26; it++) {
            int idx = it * 512 + tid;
            int s = idx % 208;
            int ic = idx / 208;
            if (s <= SLAB_PX) {           // s==204 is the zero row
                float v = 0.0f;
                if (s < SLAB_PX) {
                    int sy = s / SLAB_W, sx = s - sy * SLAB_W;
                    int yy = py0 - 1 + sy, xx = px0 - 1 + sx;
                    if ((unsigned)yy < 192u && (unsigned)xx < 192u)
                        v = __ldg(&xb[(size_t)ic * HW + yy * 192 + xx]);
                }
                __half h = __float2half_rn(v);
                __half l = __float2half_rn(v - __half2float(h));
                uint32_t off = (uint32_t)s * 128u + (((uint32_t)ic * 2u) ^ (uint32_t)((s & 7) << 4));
                *(__half*)(sm + off) = h;
                *(__half*)(sm + SLAB_BYTES + off) = l;
            }
        }
    }

    for (int c = 0; c < 18; c++) {
        CP_WAIT1();
        __syncthreads();
        if (c + 2 < 18) load_b(c + 2);
        CP_COMMIT();

        int tap = c >> 1, half = c & 1;
        int dy = tap / 3 - 1, dx = tap % 3 - 1;
        uint32_t sa[4];
#pragma unroll
        for (int mt = 0; mt < 4; mt++) {
            bool v = ((unsigned)(ry[mt] + dy) < 192u) && ((unsigned)(rx[mt] + dx) < 192u);
            sa[mt] = v ? (uint32_t)(sbs[mt] + dy * SLAB_W + dx) : (uint32_t)SLAB_ZERO;
        }
        uint32_t bst = sb + B_OFF + (uint32_t)(c % 3) * B_STAGE;
#pragma unroll
        for (int k16 = 0; k16 < 2; k16++) {
            int kb = k16 * 32;
            int acolb = half * 64 + kb + (lane >> 4) * 16;
            int brr = wn * 32 + ((lane >> 4) << 3) + (lane & 7);
            int bcolb = kb + ((lane >> 3) & 1) * 16;
            uint32_t bd_a = swz64(brr, bcolb);
            uint32_t bd_b = swz64(brr + 16, bcolb);

            uint32_t bh[4][2], bl[4][2];
            {
                uint32_t r[4];
                ldmx4(bst + bd_a, r);
                bh[0][0] = r[0]; bh[0][1] = r[1]; bh[1][0] = r[2]; bh[1][1] = r[3];
                ldmx4(bst + bd_b, r);
                bh[2][0] = r[0]; bh[2][1] = r[1]; bh[3][0] = r[2]; bh[3][1] = r[3];
                ldmx4(bst + 16384u + bd_a, r);
                bl[0][0] = r[0]; bl[0][1] = r[1]; bl[1][0] = r[2]; bl[1][1] = r[3];
                ldmx4(bst + 16384u + bd_b, r);
                bl[2][0] = r[0]; bl[2][1] = r[1]; bl[3][0] = r[2]; bl[3][1] = r[3];
            }
#pragma unroll
            for (int mt = 0; mt < 4; mt++) {
                uint32_t ah[4], al[4];
                uint32_t ad = swz128((int)sa[mt], acolb);
                ldmx4(sb + ad, ah);
                ldmx4(sb + SLAB_BYTES + ad, al);
#pragma unroll
                for (int nt = 0; nt < 4; nt++) hmma(acc[mt][nt], ah, bh[nt]);
#pragma unroll
                for (int nt = 0; nt < 4; nt++) hmma(acc[mt][nt], al, bh[nt]);
#pragma unroll
                for (int nt = 0; nt < 4; nt++) hmma(acc[mt][nt], ah, bl[nt]);
            }
        }
    }

    // ---------------- conv2 (4 x 64-oc phases), w2 preloaded once ----------------
    int wm2 = wid & 3, wn2 = wid >> 2;
    float acc2[2][2][4];
#pragma unroll
    for (int i = 0; i < 2; i++)
#pragma unroll
        for (int j = 0; j < 2; j++)
#pragma unroll
            for (int k = 0; k < 4; k++) acc2[i][j][k] = 0.0f;

    int w2row = tid >> 3, w2sg = tid & 7;
    uint32_t w2d = swz128(w2row, w2sg * 16);

    __syncthreads();
#pragma unroll
    for (int ph = 0; ph < 4; ph++) {
        cp16(sb + B_OFF + (uint32_t)ph * 16384u + w2d,
             g_w2h + (size_t)w2row * 256 + ph * 64 + w2sg * 8, 16);
        cp16(sb + B_OFF + (uint32_t)ph * 16384u + 8192u + w2d,
             g_w2l + (size_t)w2row * 256 + ph * 64 + w2sg * 8, 16);
    }
    CP_COMMIT();

    for (int ph = 0; ph < 4; ph++) {
        if (ph) __syncthreads();
        if ((wn >> 1) == ph) {
            int ocbase = (wn & 1) * 32;
#pragma unroll
            for (int mt = 0; mt < 4; mt++) {
#pragma unroll
                for (int nt = 0; nt < 4; nt++) {
                    int oc_l = ocbase + nt * 8 + (lane & 3) * 2;
                    float bb0 = __ldg(&b1[ph * 64 + oc_l]);
                    float bb1 = __ldg(&b1[ph * 64 + oc_l + 1]);
#pragma unroll
                    for (int rh = 0; rh < 2; rh++) {
                        int row = wm * 64 + mt * 16 + (lane >> 2) + rh * 8;
                        float t0 = fmaxf(acc[mt][nt][rh * 2 + 0] + bb0, 0.0f);
                        float t1 = fmaxf(acc[mt][nt][rh * 2 + 1] + bb1, 0.0f);
                        __half h0 = __float2half_rn(t0), h1 = __float2half_rn(t1);
                        uint32_t ad = (uint32_t)(row * 128 + ((oc_l * 2) ^ ((row & 7) << 4)));
                        *(__half2*)(sm + ad) = __halves2half2(h0, h1);
                        *(__half2*)(sm + 16384 + ad) = __halves2half2(
                            __float2half_rn(t0 - __half2float(h0)),
                            __float2half_rn(t1 - __half2float(h1)));
                    }
                }
            }
        }
        if (ph == 0) CP_WAIT0();
        __syncthreads();
        uint32_t wbase = sb + B_OFF + (uint32_t)ph * 16384u;
#pragma unroll
        for (int kc = 0; kc < 2; kc++) {
#pragma unroll
            for (int k16 = 0; k16 < 2; k16++) {
                int kcb = kc * 64 + k16 * 32;
                uint32_t bf2h[2][2], bf2l[2][2];
                int brow2 = wn2 * 16 + ((lane >> 4) << 3) + (lane & 7);
                int bcolb2 = kcb + ((lane >> 3) & 1) * 16;
                uint32_t bd2 = swz128(brow2, bcolb2);
                {
                    uint32_t r[4];
                    ldmx4(wbase + bd2, r);
                    bf2h[0][0] = r[0]; bf2h[0][1] = r[1]; bf2h[1][0] = r[2]; bf2h[1][1] = r[3];
                    ldmx4(wbase + 8192u + bd2, r);
                    bf2l[0][0] = r[0]; bf2l[0][1] = r[1]; bf2l[1][0] = r[2]; bf2l[1][1] = r[3];
                }
#pragma unroll
                for (int mt = 0; mt < 2; mt++) {
                    uint32_t ah[4], al[4];
                    int row = wm2 * 32 + mt * 16 + (lane & 15);
                    int colb = kcb + (lane >> 4) * 16;
                    uint32_t ad = swz128(row, colb);
                    ldmx4(sb + ad, ah);
                    ldmx4(sb + 16384u + ad, al);
#pragma unroll
                    for (int nt = 0; nt < 2; nt++) hmma(acc2[mt][nt], ah, bf2h[nt]);
#pragma unroll
                    for (int nt = 0; nt < 2; nt++) hmma(acc2[mt][nt], al, bf2h[nt]);
#pragma unroll
                    for (int nt = 0; nt < 2; nt++) hmma(acc2[mt][nt], ah, bf2l[nt]);
                }
            }
        }
    }

    // epilogue: feat = relu((D2 + b2) * (1 + union_init))
#pragma unroll
    for (int mt = 0; mt < 2; mt++) {
#pragma unroll
        for (int nt = 0; nt < 2; nt++) {
            int oc2 = wn2 * 16 + nt * 8 + (lane & 3) * 2;
            float bb0 = __ldg(&b2[oc2]), bb1 = __ldg(&b2[oc2 + 1]);
#pragma unroll
            for (int rh = 0; rh < 2; rh++) {
                int m = wm2 * 32 + mt * 16 + (lane >> 2) + rh * 8;
                int px = (py0 + (m >> 5)) * 192 + px0 + (m & 31);
                float u = g_union[b * HW + px];
                float s = 1.0f + u;
                float2 v;
                v.x = fmaxf((acc2[mt][nt][rh * 2 + 0] + bb0) * s, 0.0f);
                v.y = fmaxf((acc2[mt][nt][rh * 2 + 1] + bb1) * s, 0.0f);
                *(float2*)&g_feat[((size_t)b * HW + px) * 64 + oc2] = v;
            }
        }
    }
}

// ---------------- final: featmul pass 2 + NHWC -> NCHW ----------------
__global__ void k_final(float* __restrict__ out) {
    __shared__ float t[32][33];
    int b = blockIdx.z;
    int c0 = blockIdx.y * 32;
    int p0 = blockIdx.x * 32;
    int tx = threadIdx.x, ty = threadIdx.y;
#pragma unroll
    for (int i = 0; i < 32; i += 8) {
        int p = p0 + ty + i;
        float u = g_union[b * HW + p];
        float v = g_feat[((size_t)b * HW + p) * CIN + c0 + tx];
        t[ty + i][tx] = fmaxf(v * (1.0f + u), 0.0f);
    }
    __syncthreads();
#pragma unroll
    for (int i = 0; i < 32; i += 8)
        out[((size_t)b * CIN + c0 + ty + i) * HW + p0 + tx] = t[tx][ty + i];
}

// ---------------- bilinear sampling (NHWC), 2 CTAs per poly ----------------
__global__ __launch_bounds__(256) void k_sample(const int* __restrict__ ct_ind,
                                                const int* __restrict__ ct_img) {
    __shared__ float s_w[129][4];
    __shared__ int s_off[129][4];
    int n = blockIdx.x >> 1;
    int half = blockIdx.x & 1;
    int tid = threadIdx.x;
    int img = ct_img[n];
    if (tid < 129) {
        float ptx, pty;
        if (tid == 0) {
            int ind = ct_ind[n];
            ptx = (float)(ind % WW);
            pty = (float)(ind / WW);
        } else {
            ptx = g_init[(n * PPTS + tid - 1) * 2 + 0];
            pty = g_init[(n * PPTS + tid - 1) * 2 + 1];
        }
        float xs = ptx - 0.5f, ys = pty - 0.5f;
        float x0f = floorf(xs), y0f = floorf(ys);
        float wx = xs - x0f, wy = ys - y0f;
        int x0 = (int)x0f, y0 = (int)y0f;
#pragma unroll
        for (int k = 0; k < 4; k++) {
            int xi = x0 + (k & 1);
            int yi = y0 + (k >> 1);
            bool valid = (xi >= 0) && (xi < WW) && (yi >= 0) && (yi < HH);
            int xc = min(max(xi, 0), WW - 1);
            int yc = min(max(yi, 0), HH - 1);
            s_off[tid][k] = yc * WW + xc;
            float wxx = (k & 1) ? wx : (1.0f - wx);
            float wyy = (k >> 1) ? wy : (1.0f - wy);
            s_w[tid][k] = valid ? wxx * wyy : 0.0f;
        }
    }
    __syncthreads();
    const float* fb = g_feat + (size_t)img * HW * CIN;
    int beg = half * 4128, end = beg + 4128;
    for (int i = beg + tid; i < end; i += 256) {
        int pp = i >> 6;
        int c = i & 63;
        float v = s_w[pp][0] * fb[(size_t)s_off[pp][0] * CIN + c]
                + s_w[pp][1] * fb[(size_t)s_off[pp][1] * CIN + c]
                + s_w[pp][2] * fb[(size_t)s_off[pp][2] * CIN + c]
                + s_w[pp][3] * fb[(size_t)s_off[pp][3] * CIN + c];
        g_fp[(size_t)n * FPK + c * 129 + pp] = v;
    }
}

// ---------------- NT GEMMs for offsets (fp32, exact path) ----------------
template <int MODE>
__global__ __launch_bounds__(256) void k_gemm(const float* __restrict__ Bm,
                                              const float* __restrict__ bias,
                                              float* __restrict__ outc) {
    const int K = (MODE == 0) ? FPK : 512;
    const float* A = (MODE == 0) ? (const float*)g_fp : (const float*)g_tmp;
    __shared__ float sA[16][68];
    __shared__ float sB[16][68];
    int m0 = blockIdx.y * 64, n0 = blockIdx.x * 64;
    int tid = threadIdx.x;
    int tx = tid & 15, ty = tid >> 4;
    int kk = tid & 15, rr = tid >> 4;
    float acc[4][4];
#pragma unroll
    for (int i = 0; i < 4; i++)
#pragma unroll
        for (int j = 0; j < 4; j++) acc[i][j] = 0.0f;

    int kbeg = (MODE == 0) ? blockIdx.z * 688 : 0;
    int kend = (MODE == 0) ? kbeg + 688 : 512;
    for (int k0 = kbeg; k0 < kend; k0 += 16) {
        __syncthreads();
#pragma unroll
        for (int pass = 0; pass < 4; pass++) {
            int row = rr + pass * 16;
            sA[kk][row] = A[(size_t)(m0 + row) * K + k0 + kk];
            sB[kk][row] = Bm[(size_t)(n0 + row) * K + k0 + kk];
        }
        __syncthreads();
#pragma unroll
        for (int k2 = 0; k2 < 16; k2++) {
            float4 a4 = *(const float4*)&sA[k2][ty * 4];
            float4 b4 = *(const float4*)&sB[k2][tx * 4];
            acc[0][0] += a4.x * b4.x; acc[0][1] += a4.x * b4.y; acc[0][2] += a4.x * b4.z; acc[0][3] += a4.x * b4.w;
            acc[1][0] += a4.y * b4.x; acc[1][1] += a4.y * b4.y; acc[1][2] += a4.y * b4.z; acc[1][3] += a4.y * b4.w;
            acc[2][0] += a4.z * b4.x; acc[2][1] += a4.z * b4.y; acc[2][2] += a4.z * b4.z; acc[2][3] += a4.z * b4.w;
            acc[3][0] += a4.w * b4.x; acc[3][1] += a4.w * b4.y; acc[3][2] += a4.w * b4.z; acc[3][3] += a4.w * b4.w;
        }
    }
    if (MODE == 0) {
#pragma unroll
        for (int i = 0; i < 4; i++)
#pragma unroll
            for (int j = 0; j < 4; j++)
                g_part[((size_t)blockIdx.z * 128 + m0 + ty * 4 + i) * 512 + n0 + tx * 4 + j] = acc[i][j];
    } else {
#pragma unroll
        for (int i = 0; i < 4; i++) {
            int m = m0 + ty * 4 + i;
#pragma unroll
            for (int j = 0; j < 4; j++) {
                int nn = n0 + tx * 4 + j;
                float v = acc[i][j] + bias[nn];
                float cr = v * 4.0f + g_init[m * 256 + nn];
                g_coarse[m * 256 + nn] = cr;
                outc[m * 256 + nn] = cr * 4.0f;
            }
        }
    }
}

__global__ void k_reduce() {
    int i = blockIdx.x * 256 + threadIdx.x;
    float s = 0.0f;
#pragma unroll
    for (int p = 0; p < NSPLIT; p++) s += g_part[(size_t)p * 65536 + i];
    g_tmp[i] = s;
}

// ---------------- launcher ----------------
extern "C" void kernel_launch(void* const* d_in, const int* in_sizes, int n_in,
                              void* d_out, int out_size) {
    const float* wh     = (const float*)d_in[0];
    const float* cnn    = (const float*)d_in[1];
    const float* w1     = (const float*)d_in[2];
    const float* b1     = (const float*)d_in[3];
    const float* w2     = (const float*)d_in[4];
    const float* b2     = (const float*)d_in[5];
    const float* wpoly  = (const float*)d_in[6];
    const float* wfuse  = (const float*)d_in[7];
    const float* bfuse  = (const float*)d_in[8];
    const int*   ct_ind = (const int*)d_in[9];
    const int*   ct_img = (const int*)d_in[10];
    const int*   ct_num = (const int*)d_in[11];

    float* out        = (float*)d_out;
    float* out_init   = out + O_INIT;
    float* out_coarse = out + O_COARSE;
    float* out_mbi    = out + O_MBI;
    float* out_mbc    = out + O_MBC;
    float* out_feat   = out + O_FEAT;

    cudaFuncSetAttribute(k_conv, cudaFuncAttributeMaxDynamicSharedMemorySize, CONV_SMEM);

    k_zero<<<576, 256>>>(ct_num, out_mbi);                                  // 0
    k_init<<<128, 128>>>(wh, ct_ind, ct_img, out_init);                     // 1
    k_front<<<2176, 256>>>(w1, w2, wh, ct_ind, ct_img, ct_num, out_mbi);    // 2
    k_conv<<<dim3(288, 4), 512, CONV_SMEM>>>(cnn, b1, b2);                  // 3 <- profiled

    k_sample<<<256, 256>>>(ct_ind, ct_img);
    k_gemm<0><<<dim3(8, 2, NSPLIT), 256>>>(wpoly, nullptr, nullptr);
    k_reduce<<<256, 256>>>();
    k_gemm<1><<<dim3(4, 2), 256>>>(wfuse, bfuse, out_coarse);

    k_zero<<<576, 256>>>(ct_num, out_mbc);
    k_pnp_c<<<dim3(24, 64), 256>>>(ct_num, out_mbc);
    k_final<<<dim3(1152, 2, 4), dim3(32, 8)>>>(out_feat);
}

// round 13
// speedup vs baseline: 1.1397x; 1.1397x over previous
#include <cuda_runtime.h>
#include <cuda_fp16.h>
#include <cstdint>

// ---------------- problem constants ----------------
#define BATCH   4
#define CIN     64
#define HH      192
#define WW      192
#define HW      36864
#define NPOLY   128
#define PPTS    128
#define FPK     8256
#define NSPLIT  12

// output layout (floats)
#define O_INIT   0
#define O_COARSE 32768
#define O_MBI    65536
#define O_MBC    (65536 + 4718592)
#define O_FEAT   (65536 + 2*4718592)

// conv A-slab geometry (32x4 pixel patch, 1-px halo)
#define SLAB_W  34
#define SLAB_PX 204
#define SLAB_ZERO 204
#define SLAB_BYTES 26240u      // 205 rows * 128 B
#define B_OFF   52480u         // 2 * SLAB_BYTES
#define B_STAGE 32768u
#define CONV_SMEM (52480 + 3*32768)   // 150784

// ---------------- device scratch ----------------
__device__ __half g_xh_h[BATCH * HW * CIN];
__device__ __half g_xh_l[BATCH * HW * CIN];
__device__ __half g_w1h[256 * 576];
__device__ __half g_w1l[256 * 576];
__device__ __half g_w2h[64 * 256];
__device__ __half g_w2l[64 * 256];
__device__ float  g_feat[BATCH * HW * CIN];
__device__ float  g_union[BATCH * HW];
__device__ float  g_init[NPOLY * PPTS * 2];
__device__ float  g_coarse[NPOLY * PPTS * 2];
__device__ float  g_fp[NPOLY * FPK];
__device__ float  g_tmp[NPOLY * 512];
__device__ float  g_part[NSPLIT * NPOLY * 512];

// ---------------- helpers ----------------
__device__ __forceinline__ uint32_t smem_u32(const void* p) {
    uint32_t a;
    asm("{ .reg .u64 t; cvta.to.shared.u64 t, %1; cvt.u32.u64 %0, t; }" : "=r"(a) : "l"(p));
    return a;
}
__device__ __forceinline__ void cp16(uint32_t dst, const void* src, int sz) {
    asm volatile("cp.async.ca.shared.global [%0], [%1], 16, %2;" :: "r"(dst), "l"(src), "r"(sz));
}
#define CP_COMMIT() asm volatile("cp.async.commit_group;")
#define CP_WAIT1()  asm volatile("cp.async.wait_group 1;")
#define CP_WAIT0()  asm volatile("cp.async.wait_group 0;")
__device__ __forceinline__ void ldmx4(uint32_t addr, uint32_t* r) {
    asm volatile("ldmatrix.sync.aligned.m8n8.x4.shared.b16 {%0,%1,%2,%3}, [%4];"
        : "=r"(r[0]), "=r"(r[1]), "=r"(r[2]), "=r"(r[3]) : "r"(addr));
}
__device__ __forceinline__ void hmma(float* d, const uint32_t* a, const uint32_t* b) {
    asm volatile("mma.sync.aligned.m16n8k16.row.col.f32.f16.f16.f32 "
        "{%0,%1,%2,%3}, {%4,%5,%6,%7}, {%8,%9}, {%0,%1,%2,%3};"
        : "+f"(d[0]), "+f"(d[1]), "+f"(d[2]), "+f"(d[3])
        : "r"(a[0]), "r"(a[1]), "r"(a[2]), "r"(a[3]), "r"(b[0]), "r"(b[1]));
}
__device__ __forceinline__ uint32_t swz64(int row, int colb) {
    return (uint32_t)(row * 64 + (colb ^ (((row >> 1) & 3) << 4)));
}
__device__ __forceinline__ uint32_t swz128(int row, int colb) {
    return (uint32_t)(row * 128 + (colb ^ ((row & 7) << 4)));
}
__device__ __forceinline__ void split_store(__half* hp, __half* lp, float v) {
    __half h = __float2half_rn(v);
    *hp = h;
    *lp = __float2half_rn(v - __half2float(h));
}

// ---------------- zero kernel: union + mb slack slots ----------------
__global__ void k_zero(const int* __restrict__ ct_num, float* __restrict__ mb) {
    int i = blockIdx.x * 256 + threadIdx.x;
    ((unsigned*)g_union)[i] = 0u;
    int b = i / HW, px = i - b * HW;
    int cn = ct_num[b];
    for (int c = cn; c < 32; c++)
        mb[(size_t)(b * 32 + c) * HW + px] = 0.0f;
}

// ---------------- pnp body ----------------
__device__ void pnp_body(int poly, int rg, int src,
                         const float* __restrict__ wh, const int* __restrict__ ct_ind,
                         const int* __restrict__ ct_img, const int* __restrict__ ct_num,
                         float* __restrict__ mb) {
    __shared__ float verts[256];
    __shared__ float xint[8][132];
    __shared__ int cnt[8];
    __shared__ int slots[4];
    int tid = threadIdx.x;
    int rb = rg * 8;

    if (src == 0) {
        int ind = ct_ind[poly];
        int img = ct_img[poly];
        int cx = ind % WW;
        int cy = ind / WW;
        int p = tid >> 1;
        size_t base = (size_t)img * 256 * HW + (size_t)cy * WW + cx;
        float off = wh[base + (size_t)(2 * p + (tid & 1)) * HW];
        verts[tid] = off * 10.0f + (float)((tid & 1) ? cy : cx);
    } else {
        verts[tid] = g_coarse[poly * 256 + tid];
    }
    if (tid < 8) cnt[tid] = 0;
    if (tid < 4) {
        int cnb = ct_num[tid];
        int start = (tid == 0) ? 0 : ct_num[tid - 1];   // reference slicing quirk
        int c = poly - start;
        slots[tid] = (c >= 0 && c < cnb) ? c : -1;
    }
    __syncthreads();
    for (int i = tid; i < 1024; i += 256) {
        int e = i & 127, r = i >> 7;
        float yy = (float)(rb + r);
        int e2 = (e + 1) & 127;
        float y1 = verts[2 * e + 1];
        float y2 = verts[2 * e2 + 1];
        if ((y1 > yy) != (y2 > yy)) {
            float x1 = verts[2 * e];
            float x2 = verts[2 * e2];
            float den = y2 - y1;
            if (fabsf(den) < 1e-9f) den = 1e-9f;
            float xi = x1 + (x2 - x1) * (yy - y1) / den;
            int s = atomicAdd(&cnt[r], 1);
            xint[r][s] = xi;
        }
    }
    __syncthreads();
    for (int i = tid; i < 1536; i += 256) {
        int r = i / 192;
        int xp = i - r * 192;
        int c = cnt[r];
        float fx = (float)xp;
        unsigned par = 0;
        for (int j = 0; j < c; j++) par ^= (fx < xint[r][j]) ? 1u : 0u;
        float parf = (float)par;
        int px = (rb + r) * WW + xp;
#pragma unroll
        for (int b = 0; b < 4; b++) {
            int sc = slots[b];
            if (sc >= 0) {
                mb[(size_t)(b * 32 + sc) * HW + px] = parf;
                if (par) atomicOr((unsigned*)&g_union[b * HW + px], 0x3F800000u);
            }
        }
    }
}

// ---------------- K0: init polys ----------------
__global__ void k_init(const float* __restrict__ wh, const int* __restrict__ ct_ind,
                       const int* __restrict__ ct_img, float* __restrict__ out_init) {
    int n = blockIdx.x;
    int p = threadIdx.x;
    int ind = ct_ind[n];
    int img = ct_img[n];
    int cx = ind % WW;
    int cy = ind / WW;
    size_t base = (size_t)img * 256 * HW + (size_t)cy * WW + cx;
    float ox = wh[base + (size_t)(2 * p) * HW];
    float oy = wh[base + (size_t)(2 * p + 1) * HW];
    float ix = ox * 10.0f + (float)cx;
    float iy = oy * 10.0f + (float)cy;
    int o = (n * PPTS + p) * 2;
    g_init[o + 0] = ix;
    g_init[o + 1] = iy;
    out_init[o + 0] = ix * 4.0f;
    out_init[o + 1] = iy * 4.0f;
}

// ---------------- merged front ----------------
__global__ __launch_bounds__(256) void k_front(const float* __restrict__ x,
                                               const float* __restrict__ w1,
                                               const float* __restrict__ w2,
                                               const float* __restrict__ wh,
                                               const int* __restrict__ ct_ind,
                                               const int* __restrict__ ct_img,
                                               const int* __restrict__ ct_num,
                                               float* __restrict__ out_mbi) {
    int bid = blockIdx.x;
    if (bid < 640) {
        int i = bid * 256 + threadIdx.x;
        if (i < 147456) {
            int oc = i / 576, k = i - oc * 576;
            int tap = k >> 6, ic = k & 63;
            split_store(&g_w1h[i], &g_w1l[i], w1[(oc * 64 + ic) * 9 + tap]);
        } else {
            int j = i - 147456;
            split_store(&g_w2h[j], &g_w2l[j], w2[j]);
        }
        return;
    }
    if (bid < 9856) {
        __shared__ float t[32][33];
        int xb = bid - 640;
        int pxb = xb % 1152;
        int cy = (xb / 1152) & 1;
        int b = xb / 2304;
        int c0 = cy * 32;
        int p0 = pxb * 32;
        int tx = threadIdx.x & 31, ty = threadIdx.x >> 5;
#pragma unroll
        for (int i = 0; i < 32; i += 8)
            t[ty + i][tx] = x[((size_t)b * CIN + c0 + ty + i) * HW + p0 + tx];
        __syncthreads();
#pragma unroll
        for (int i = 0; i < 32; i += 8) {
            size_t o = ((size_t)b * HW + p0 + ty + i) * CIN + c0 + tx;
            split_store(&g_xh_h[o], &g_xh_l[o], t[tx][ty + i]);
        }
        return;
    }
    int j = bid - 9856;
    pnp_body(j % 64, j / 64, 0, wh, ct_ind, ct_img, ct_num, out_mbi);
}

// ---------------- pnp(coarse) ----------------
__global__ __launch_bounds__(256) void k_pnp_c(const int* __restrict__ ct_num,
                                               float* __restrict__ out_mbc) {
    pnp_body(blockIdx.y, blockIdx.x, 1, nullptr, nullptr, nullptr, ct_num, out_mbc);
}

// ---------------- fused conv1 + conv2 (+featmul) ----------------
__global__ __launch_bounds__(512, 1) void k_conv(const float* __restrict__ b1,
                                                 const float* __restrict__ b2) {
    extern __shared__ char sm[];
    uint32_t sb = smem_u32(sm);
    int tid = threadIdx.x, lane = tid & 31, wid = tid >> 5;
    int b = blockIdx.y;
    int px0 = (blockIdx.x % 6) * 32;
    int py0 = (blockIdx.x / 6) * 4;
    int wm = wid & 1, wn = wid >> 1;

    float acc[4][4][4];
#pragma unroll
    for (int i = 0; i < 4; i++)
#pragma unroll
        for (int j = 0; j < 4; j++)
#pragma unroll
            for (int k = 0; k < 4; k++) acc[i][j][k] = 0.0f;

    size_t xbase = (size_t)b * HW;

    int ry[4], rx[4], sbs[4];
#pragma unroll
    for (int mt = 0; mt < 4; mt++) {
        int r = wm * 64 + mt * 16 + (lane & 15);
        int pr = r >> 5, pc = r & 31;
        ry[mt] = py0 + pr;
        rx[mt] = px0 + pc;
        sbs[mt] = (pr + 1) * SLAB_W + pc + 1;
    }

    int brow = tid >> 1;
    int bq0 = (tid & 1) * 2;
    const __half* w1h_p = g_w1h + (size_t)brow * 576 + bq0 * 8;
    const __half* w1l_p = g_w1l + (size_t)brow * 576 + bq0 * 8;
    uint32_t bd0 = swz64(brow, bq0 * 16);
    uint32_t bd1 = swz64(brow, bq0 * 16 + 16);

    auto load_b = [&](int chunk) {
        uint32_t st = sb + B_OFF + (uint32_t)(chunk % 3) * B_STAGE;
        int tap = chunk >> 1, half = chunk & 1;
        int wo = tap * 64 + half * 32;
        cp16(st + bd0, w1h_p + wo, 16);
        cp16(st + bd1, w1h_p + wo + 8, 16);
        cp16(st + 16384u + bd0, w1l_p + wo, 16);
        cp16(st + 16384u + bd1, w1l_p + wo + 8, 16);
    };

    for (int i = tid; i < 205 * 8; i += 512) {
        int s = i >> 3, q = i & 7;
        uint32_t d = swz128(s, q * 16);
        int sz = 0;
        size_t np = 0;
        if (s < SLAB_PX) {
            int sy = s / SLAB_W, sx = s - sy * SLAB_W;
            int yy = py0 - 1 + sy, xx = px0 - 1 + sx;
            if ((unsigned)yy < 192u && (unsigned)xx < 192u) {
                np = (xbase + yy * 192 + xx) * 64 + q * 8;
                sz = 16;
            }
        }
        cp16(sb + d, g_xh_h + np, sz);
        cp16(sb + SLAB_BYTES + d, g_xh_l + np, sz);
    }
    load_b(0); CP_COMMIT();
    load_b(1); CP_COMMIT();

    for (int c = 0; c < 18; c++) {
        CP_WAIT1();
        __syncthreads();
        if (c + 2 < 18) load_b(c + 2);
        CP_COMMIT();

        int tap = c >> 1, half = c & 1;
        int dy = tap / 3 - 1, dx = tap % 3 - 1;
        uint32_t sa[4];
#pragma unroll
        for (int mt = 0; mt < 4; mt++) {
            bool v = ((unsigned)(ry[mt] + dy) < 192u) && ((unsigned)(rx[mt] + dx) < 192u);
            sa[mt] = v ? (uint32_t)(sbs[mt] + dy * SLAB_W + dx) : (uint32_t)SLAB_ZERO;
        }
        uint32_t bst = sb + B_OFF + (uint32_t)(c % 3) * B_STAGE;
#pragma unroll
        for (int k16 = 0; k16 < 2; k16++) {
            int kb = k16 * 32;
            int acolb = half * 64 + kb + (lane >> 4) * 16;
            int brr = wn * 32 + ((lane >> 4) << 3) + (lane & 7);
            int bcolb = kb + ((lane >> 3) & 1) * 16;
            uint32_t bd_a = swz64(brr, bcolb);
            uint32_t bd_b = swz64(brr + 16, bcolb);

            uint32_t bh[4][2], bl[4][2];
            {
                uint32_t r[4];
                ldmx4(bst + bd_a, r);
                bh[0][0] = r[0]; bh[0][1] = r[1]; bh[1][0] = r[2]; bh[1][1] = r[3];
                ldmx4(bst + bd_b, r);
                bh[2][0] = r[0]; bh[2][1] = r[1]; bh[3][0] = r[2]; bh[3][1] = r[3];
                ldmx4(bst + 16384u + bd_a, r);
                bl[0][0] = r[0]; bl[0][1] = r[1]; bl[1][0] = r[2]; bl[1][1] = r[3];
                ldmx4(bst + 16384u + bd_b, r);
                bl[2][0] = r[0]; bl[2][1] = r[1]; bl[3][0] = r[2]; bl[3][1] = r[3];
            }
#pragma unroll
            for (int mt = 0; mt < 4; mt++) {
                uint32_t ah[4], al[4];
                uint32_t ad = swz128((int)sa[mt], acolb);
                ldmx4(sb + ad, ah);
                ldmx4(sb + SLAB_BYTES + ad, al);
#pragma unroll
                for (int nt = 0; nt < 4; nt++) hmma(acc[mt][nt], ah, bh[nt]);
#pragma unroll
                for (int nt = 0; nt < 4; nt++) hmma(acc[mt][nt], al, bh[nt]);
#pragma unroll
                for (int nt = 0; nt < 4; nt++) hmma(acc[mt][nt], ah, bl[nt]);
            }
        }
    }

    // ---------------- conv2 (4 x 64-oc phases), w2 preloaded once ----------------
    int wm2 = wid & 3, wn2 = wid >> 2;
    float acc2[2][2][4];
#pragma unroll
    for (int i = 0; i < 2; i++)
#pragma unroll
        for (int j = 0; j < 2; j++)
#pragma unroll
            for (int k = 0; k < 4; k++) acc2[i][j][k] = 0.0f;

    int w2row = tid >> 3, w2sg = tid & 7;
    uint32_t w2d = swz128(w2row, w2sg * 16);

    __syncthreads();
#pragma unroll
    for (int ph = 0; ph < 4; ph++) {
        cp16(sb + B_OFF + (uint32_t)ph * 16384u + w2d,
             g_w2h + (size_t)w2row * 256 + ph * 64 + w2sg * 8, 16);
        cp16(sb + B_OFF + (uint32_t)ph * 16384u + 8192u + w2d,
             g_w2l + (size_t)w2row * 256 + ph * 64 + w2sg * 8, 16);
    }
    CP_COMMIT();

    for (int ph = 0; ph < 4; ph++) {
        if (ph) __syncthreads();
        if ((wn >> 1) == ph) {
            int ocbase = (wn & 1) * 32;
#pragma unroll
            for (int mt = 0; mt < 4; mt++) {
#pragma unroll
                for (int nt = 0; nt < 4; nt++) {
                    int oc_l = ocbase + nt * 8 + (lane & 3) * 2;
                    float bb0 = __ldg(&b1[ph * 64 + oc_l]);
                    float bb1 = __ldg(&b1[ph * 64 + oc_l + 1]);
#pragma unroll
                    for (int rh = 0; rh < 2; rh++) {
                        int row = wm * 64 + mt * 16 + (lane >> 2) + rh * 8;
                        float t0 = fmaxf(acc[mt][nt][rh * 2 + 0] + bb0, 0.0f);
                        float t1 = fmaxf(acc[mt][nt][rh * 2 + 1] + bb1, 0.0f);
                        __half h0 = __float2half_rn(t0), h1 = __float2half_rn(t1);
                        uint32_t ad = (uint32_t)(row * 128 + ((oc_l * 2) ^ ((row & 7) << 4)));
                        *(__half2*)(sm + ad) = __halves2half2(h0, h1);
                        *(__half2*)(sm + 16384 + ad) = __halves2half2(
                            __float2half_rn(t0 - __half2float(h0)),
                            __float2half_rn(t1 - __half2float(h1)));
                    }
                }
            }
        }
        if (ph == 0) CP_WAIT0();
        __syncthreads();
        uint32_t wbase = sb + B_OFF + (uint32_t)ph * 16384u;
#pragma unroll
        for (int kc = 0; kc < 2; kc++) {
#pragma unroll
            for (int k16 = 0; k16 < 2; k16++) {
                int kcb = kc * 64 + k16 * 32;
                uint32_t bf2h[2][2], bf2l[2][2];
                int brow2 = wn2 * 16 + ((lane >> 4) << 3) + (lane & 7);
                int bcolb2 = kcb + ((lane >> 3) & 1) * 16;
                uint32_t bd2 = swz128(brow2, bcolb2);
                {
                    uint32_t r[4];
                    ldmx4(wbase + bd2, r);
                    bf2h[0][0] = r[0]; bf2h[0][1] = r[1]; bf2h[1][0] = r[2]; bf2h[1][1] = r[3];
                    ldmx4(wbase + 8192u + bd2, r);
                    bf2l[0][0] = r[0]; bf2l[0][1] = r[1]; bf2l[1][0] = r[2]; bf2l[1][1] = r[3];
                }
#pragma unroll
                for (int mt = 0; mt < 2; mt++) {
                    uint32_t ah[4], al[4];
                    int row = wm2 * 32 + mt * 16 + (lane & 15);
                    int colb = kcb + (lane >> 4) * 16;
                    uint32_t ad = swz128(row, colb);
                    ldmx4(sb + ad, ah);
                    ldmx4(sb + 16384u + ad, al);
#pragma unroll
                    for (int nt = 0; nt < 2; nt++) hmma(acc2[mt][nt], ah, bf2h[nt]);
#pragma unroll
                    for (int nt = 0; nt < 2; nt++) hmma(acc2[mt][nt], al, bf2h[nt]);
#pragma unroll
                    for (int nt = 0; nt < 2; nt++) hmma(acc2[mt][nt], ah, bf2l[nt]);
                }
            }
        }
    }

    // epilogue: feat = relu((D2 + b2) * (1 + union_init))
#pragma unroll
    for (int mt = 0; mt < 2; mt++) {
#pragma unroll
        for (int nt = 0; nt < 2; nt++) {
            int oc2 = wn2 * 16 + nt * 8 + (lane & 3) * 2;
            float bb0 = __ldg(&b2[oc2]), bb1 = __ldg(&b2[oc2 + 1]);
#pragma unroll
            for (int rh = 0; rh < 2; rh++) {
                int m = wm2 * 32 + mt * 16 + (lane >> 2) + rh * 8;
                int px = (py0 + (m >> 5)) * 192 + px0 + (m & 31);
                float u = g_union[b * HW + px];
                float s = 1.0f + u;
                float2 v;
                v.x = fmaxf((acc2[mt][nt][rh * 2 + 0] + bb0) * s, 0.0f);
                v.y = fmaxf((acc2[mt][nt][rh * 2 + 1] + bb1) * s, 0.0f);
                *(float2*)&g_feat[((size_t)b * HW + px) * 64 + oc2] = v;
            }
        }
    }
}

// ---------------- final: featmul pass 2 + NHWC -> NCHW ----------------
__global__ void k_final(float* __restrict__ out) {
    __shared__ float t[32][33];
    int b = blockIdx.z;
    int c0 = blockIdx.y * 32;
    int p0 = blockIdx.x * 32;
    int tx = threadIdx.x, ty = threadIdx.y;
#pragma unroll
    for (int i = 0; i < 32; i += 8) {
        int p = p0 + ty + i;
        float u = g_union[b * HW + p];
        float v = g_feat[((size_t)b * HW + p) * CIN + c0 + tx];
        t[ty + i][tx] = fmaxf(v * (1.0f + u), 0.0f);
    }
    __syncthreads();
#pragma unroll
    for (int i = 0; i < 32; i += 8)
        out[((size_t)b * CIN + c0 + ty + i) * HW + p0 + tx] = t[tx][ty + i];
}

// ---------------- bilinear sampling (NHWC), 2 CTAs per poly ----------------
__global__ __launch_bounds__(256) void k_sample(const int* __restrict__ ct_ind,
                                                const int* __restrict__ ct_img) {
    __shared__ float s_w[129][4];
    __shared__ int s_off[129][4];
    int n = blockIdx.x >> 1;
    int half = blockIdx.x & 1;
    int tid = threadIdx.x;
    int img = ct_img[n];
    if (tid < 129) {
        float ptx, pty;
        if (tid == 0) {
            int ind = ct_ind[n];
            ptx = (float)(ind % WW);
            pty = (float)(ind / WW);
        } else {
            ptx = g_init[(n * PPTS + tid - 1) * 2 + 0];
            pty = g_init[(n * PPTS + tid - 1) * 2 + 1];
        }
        float xs = ptx - 0.5f, ys = pty - 0.5f;
        float x0f = floorf(xs), y0f = floorf(ys);
        float wx = xs - x0f, wy = ys - y0f;
        int x0 = (int)x0f, y0 = (int)y0f;
#pragma unroll
        for (int k = 0; k < 4; k++) {
            int xi = x0 + (k & 1);
            int yi = y0 + (k >> 1);
            bool valid = (xi >= 0) && (xi < WW) && (yi >= 0) && (yi < HH);
            int xc = min(max(xi, 0), WW - 1);
            int yc = min(max(yi, 0), HH - 1);
            s_off[tid][k] = yc * WW + xc;
            float wxx = (k & 1) ? wx : (1.0f - wx);
            float wyy = (k >> 1) ? wy : (1.0f - wy);
            s_w[tid][k] = valid ? wxx * wyy : 0.0f;
        }
    }
    __syncthreads();
    const float* fb = g_feat + (size_t)img * HW * CIN;
    int beg = half * 4128, end = beg + 4128;
    for (int i = beg + tid; i < end; i += 256) {
        int pp = i >> 6;
        int c = i & 63;
        float v = s_w[pp][0] * fb[(size_t)s_off[pp][0] * CIN + c]
                + s_w[pp][1] * fb[(size_t)s_off[pp][1] * CIN + c]
                + s_w[pp][2] * fb[(size_t)s_off[pp][2] * CIN + c]
                + s_w[pp][3] * fb[(size_t)s_off[pp][3] * CIN + c];
        g_fp[(size_t)n * FPK + c * 129 + pp] = v;
    }
}

// ---------------- NT GEMMs for offsets (fp32, exact path) ----------------
template <int MODE>
__global__ __launch_bounds__(256) void k_gemm(const float* __restrict__ Bm,
                                              const float* __restrict__ bias,
                                              float* __restrict__ outc) {
    const int K = (MODE == 0) ? FPK : 512;
    const float* A = (MODE == 0) ? (const float*)g_fp : (const float*)g_tmp;
    __shared__ float sA[16][68];
    __shared__ float sB[16][68];
    int m0 = blockIdx.y * 64, n0 = blockIdx.x * 64;
    int tid = threadIdx.x;
    int tx = tid & 15, ty = tid >> 4;
    int kk = tid & 15, rr = tid >> 4;
    float acc[4][4];
#pragma unroll
    for (int i = 0; i < 4; i++)
#pragma unroll
        for (int j = 0; j < 4; j++) acc[i][j] = 0.0f;

    int kbeg = (MODE == 0) ? blockIdx.z * 688 : 0;
    int kend = (MODE == 0) ? kbeg + 688 : 512;
    for (int k0 = kbeg; k0 < kend; k0 += 16) {
        __syncthreads();
#pragma unroll
        for (int pass = 0; pass < 4; pass++) {
            int row = rr + pass * 16;
            sA[kk][row] = A[(size_t)(m0 + row) * K + k0 + kk];
            sB[kk][row] = Bm[(size_t)(n0 + row) * K + k0 + kk];
        }
        __syncthreads();
#pragma unroll
        for (int k2 = 0; k2 < 16; k2++) {
            float4 a4 = *(const float4*)&sA[k2][ty * 4];
            float4 b4 = *(const float4*)&sB[k2][tx * 4];
            acc[0][0] += a4.x * b4.x; acc[0][1] += a4.x * b4.y; acc[0][2] += a4.x * b4.z; acc[0][3] += a4.x * b4.w;
            acc[1][0] += a4.y * b4.x; acc[1][1] += a4.y * b4.y; acc[1][2] += a4.y * b4.z; acc[1][3] += a4.y * b4.w;
            acc[2][0] += a4.z * b4.x; acc[2][1] += a4.z * b4.y; acc[2][2] += a4.z * b4.z; acc[2][3] += a4.z * b4.w;
            acc[3][0] += a4.w * b4.x; acc[3][1] += a4.w * b4.y; acc[3][2] += a4.w * b4.z; acc[3][3] += a4.w * b4.w;
        }
    }
    if (MODE == 0) {
#pragma unroll
        for (int i = 0; i < 4; i++)
#pragma unroll
            for (int j = 0; j < 4; j++)
                g_part[((size_t)blockIdx.z * 128 + m0 + ty * 4 + i) * 512 + n0 + tx * 4 + j] = acc[i][j];
    } else {
#pragma unroll
        for (int i = 0; i < 4; i++) {
            int m = m0 + ty * 4 + i;
#pragma unroll
            for (int j = 0; j < 4; j++) {
                int nn = n0 + tx * 4 + j;
                float v = acc[i][j] + bias[nn];
                float cr = v * 4.0f + g_init[m * 256 + nn];
                g_coarse[m * 256 + nn] = cr;
                outc[m * 256 + nn] = cr * 4.0f;
            }
        }
    }
}

__global__ void k_reduce() {
    int i = blockIdx.x * 256 + threadIdx.x;
    float s = 0.0f;
#pragma unroll
    for (int p = 0; p < NSPLIT; p++) s += g_part[(size_t)p * 65536 + i];
    g_tmp[i] = s;
}

// ---------------- launcher ----------------
extern "C" void kernel_launch(void* const* d_in, const int* in_sizes, int n_in,
                              void* d_out, int out_size) {
    const float* wh     = (const float*)d_in[0];
    const float* cnn    = (const float*)d_in[1];
    const float* w1     = (const float*)d_in[2];
    const float* b1     = (const float*)d_in[3];
    const float* w2     = (const float*)d_in[4];
    const float* b2     = (const float*)d_in[5];
    const float* wpoly  = (const float*)d_in[6];
    const float* wfuse  = (const float*)d_in[7];
    const float* bfuse  = (const float*)d_in[8];
    const int*   ct_ind = (const int*)d_in[9];
    const int*   ct_img = (const int*)d_in[10];
    const int*   ct_num = (const int*)d_in[11];

    float* out        = (float*)d_out;
    float* out_init   = out + O_INIT;
    float* out_coarse = out + O_COARSE;
    float* out_mbi    = out + O_MBI;
    float* out_mbc    = out + O_MBC;
    float* out_feat   = out + O_FEAT;

    cudaFuncSetAttribute(k_conv, cudaFuncAttributeMaxDynamicSharedMemorySize, CONV_SMEM);

    k_zero<<<576, 256>>>(ct_num, out_mbi);                        // 0
    k_init<<<128, 128>>>(wh, ct_ind, ct_img, out_init);           // 1
    k_front<<<11392, 256>>>(cnn, w1, w2, wh, ct_ind, ct_img, ct_num, out_mbi);  // 2
    k_conv<<<dim3(288, 4), 512, CONV_SMEM>>>(b1, b2);             // 3 <- profiled

    k_sample<<<256, 256>>>(ct_ind, ct_img);
    k_gemm<0><<<dim3(8, 2, NSPLIT), 256>>>(wpoly, nullptr, nullptr);
    k_reduce<<<256, 256>>>();
    k_gemm<1><<<dim3(4, 2), 256>>>(wfuse, bfuse, out_coarse);

    k_zero<<<576, 256>>>(ct_num, out_mbc);
    k_pnp_c<<<dim3(24, 64), 256>>>(ct_num, out_mbc);
    k_final<<<dim3(1152, 2, 4), dim3(32, 8)>>>(out_feat);
}

// round 15
// speedup vs baseline: 1.1439x; 1.0037x over previous
#include <cuda_runtime.h>
#include <cuda_fp16.h>
#include <cstdint>

// ---------------- problem constants ----------------
#define BATCH   4
#define CIN     64
#define HH      192
#define WW      192
#define HW      36864
#define NPOLY   128
#define PPTS    128
#define FPK     8256
#define NSPLIT  12

// output layout (floats)
#define O_INIT   0
#define O_COARSE 32768
#define O_MBI    65536
#define O_MBC    (65536 + 4718592)
#define O_FEAT   (65536 + 2*4718592)

// conv A-slab geometry (32x4 pixel patch, 1-px halo)
#define SLAB_W  34
#define SLAB_PX 204
#define SLAB_ZERO 204
#define SLAB_BYTES 26240u      // 205 rows * 128 B
#define B_OFF   52480u         // 2 * SLAB_BYTES
#define B_STAGE 32768u
#define CONV_SMEM (52480 + 3*32768)   // 150784

// ---------------- device scratch ----------------
__device__ __half g_xh_h[BATCH * HW * CIN];
__device__ __half g_xh_l[BATCH * HW * CIN];
__device__ __half g_w1h[256 * 576];
__device__ __half g_w1l[256 * 576];
__device__ __half g_w2h[64 * 256];
__device__ __half g_w2l[64 * 256];
__device__ float  g_feat[BATCH * HW * CIN];
__device__ float  g_union[BATCH * HW];
__device__ float  g_init[NPOLY * PPTS * 2];
__device__ float  g_coarse[NPOLY * PPTS * 2];
__device__ float  g_fp[NPOLY * FPK];
__device__ float  g_tmp[NPOLY * 512];
__device__ float  g_part[NSPLIT * NPOLY * 512];

// ---------------- helpers ----------------
__device__ __forceinline__ uint32_t smem_u32(const void* p) {
    uint32_t a;
    asm("{ .reg .u64 t; cvta.to.shared.u64 t, %1; cvt.u32.u64 %0, t; }" : "=r"(a) : "l"(p));
    return a;
}
__device__ __forceinline__ void cp16(uint32_t dst, const void* src, int sz) {
    asm volatile("cp.async.ca.shared.global [%0], [%1], 16, %2;" :: "r"(dst), "l"(src), "r"(sz));
}
#define CP_COMMIT() asm volatile("cp.async.commit_group;")
#define CP_WAIT1()  asm volatile("cp.async.wait_group 1;")
#define CP_WAIT0()  asm volatile("cp.async.wait_group 0;")
__device__ __forceinline__ void ldmx4(uint32_t addr, uint32_t* r) {
    asm volatile("ldmatrix.sync.aligned.m8n8.x4.shared.b16 {%0,%1,%2,%3}, [%4];"
        : "=r"(r[0]), "=r"(r[1]), "=r"(r[2]), "=r"(r[3]) : "r"(addr));
}
__device__ __forceinline__ void hmma(float* d, const uint32_t* a, const uint32_t* b) {
    asm volatile("mma.sync.aligned.m16n8k16.row.col.f32.f16.f16.f32 "
        "{%0,%1,%2,%3}, {%4,%5,%6,%7}, {%8,%9}, {%0,%1,%2,%3};"
        : "+f"(d[0]), "+f"(d[1]), "+f"(d[2]), "+f"(d[3])
        : "r"(a[0]), "r"(a[1]), "r"(a[2]), "r"(a[3]), "r"(b[0]), "r"(b[1]));
}
__device__ __forceinline__ uint32_t swz64(int row, int colb) {
    return (uint32_t)(row * 64 + (colb ^ (((row >> 1) & 3) << 4)));
}
__device__ __forceinline__ uint32_t swz128(int row, int colb) {
    return (uint32_t)(row * 128 + (colb ^ ((row & 7) << 4)));
}
__device__ __forceinline__ void split_store(__half* hp, __half* lp, float v) {
    __half h = __float2half_rn(v);
    *hp = h;
    *lp = __float2half_rn(v - __half2float(h));
}

// ---------------- pnp body ----------------
__device__ void pnp_body(int poly, int rg, int src,
                         const float* __restrict__ wh, const int* __restrict__ ct_ind,
                         const int* __restrict__ ct_img, const int* __restrict__ ct_num,
                         float* __restrict__ mb) {
    __shared__ float verts[256];
    __shared__ float xint[8][132];
    __shared__ int cnt[8];
    __shared__ int slots[4];
    int tid = threadIdx.x;
    int rb = rg * 8;

    if (src == 0) {
        int ind = ct_ind[poly];
        int img = ct_img[poly];
        int cx = ind % WW;
        int cy = ind / WW;
        int p = tid >> 1;
        size_t base = (size_t)img * 256 * HW + (size_t)cy * WW + cx;
        float off = wh[base + (size_t)(2 * p + (tid & 1)) * HW];
        verts[tid] = off * 10.0f + (float)((tid & 1) ? cy : cx);
    } else {
        verts[tid] = g_coarse[poly * 256 + tid];
    }
    if (tid < 8) cnt[tid] = 0;
    if (tid < 4) {
        int cnb = ct_num[tid];
        int start = (tid == 0) ? 0 : ct_num[tid - 1];   // reference slicing quirk
        int c = poly - start;
        slots[tid] = (c >= 0 && c < cnb) ? c : -1;
    }
    __syncthreads();
    for (int i = tid; i < 1024; i += 256) {
        int e = i & 127, r = i >> 7;
        float yy = (float)(rb + r);
        int e2 = (e + 1) & 127;
        float y1 = verts[2 * e + 1];
        float y2 = verts[2 * e2 + 1];
        if ((y1 > yy) != (y2 > yy)) {
            float x1 = verts[2 * e];
            float x2 = verts[2 * e2];
            float den = y2 - y1;
            if (fabsf(den) < 1e-9f) den = 1e-9f;
            float xi = x1 + (x2 - x1) * (yy - y1) / den;
            int s = atomicAdd(&cnt[r], 1);
            xint[r][s] = xi;
        }
    }
    __syncthreads();
    for (int i = tid; i < 1536; i += 256) {
        int r = i / 192;
        int xp = i - r * 192;
        int c = cnt[r];
        float fx = (float)xp;
        unsigned par = 0;
        for (int j = 0; j < c; j++) par ^= (fx < xint[r][j]) ? 1u : 0u;
        float parf = (float)par;
        int px = (rb + r) * WW + xp;
#pragma unroll
        for (int b = 0; b < 4; b++) {
            int sc = slots[b];
            if (sc >= 0) {
                mb[(size_t)(b * 32 + sc) * HW + px] = parf;
                if (par) atomicOr((unsigned*)&g_union[b * HW + px], 0x3F800000u);
            }
        }
    }
}

// ---------------- K0: init polys + init-side zeroing ----------------
__global__ void k_init(const float* __restrict__ wh, const int* __restrict__ ct_ind,
                       const int* __restrict__ ct_img, float* __restrict__ out_init,
                       const int* __restrict__ ct_num, float* __restrict__ out_mbi) {
    int n = blockIdx.x;
    int p = threadIdx.x;
    int ind = ct_ind[n];
    int img = ct_img[n];
    int cx = ind % WW;
    int cy = ind / WW;
    size_t base = (size_t)img * 256 * HW + (size_t)cy * WW + cx;
    float ox = wh[base + (size_t)(2 * p) * HW];
    float oy = wh[base + (size_t)(2 * p + 1) * HW];
    float ix = ox * 10.0f + (float)cx;
    float iy = oy * 10.0f + (float)cy;
    int o = (n * PPTS + p) * 2;
    g_init[o + 0] = ix;
    g_init[o + 1] = iy;
    out_init[o + 0] = ix * 4.0f;
    out_init[o + 1] = iy * 4.0f;
    // zero union + mb_i slack slots (16384 threads total)
    int t = blockIdx.x * 128 + threadIdx.x;
    for (int i = t; i < BATCH * HW; i += 16384)
        ((unsigned*)g_union)[i] = 0u;
#pragma unroll
    for (int b = 0; b < 4; b++) {
        int cn = ct_num[b];
        for (int c = cn; c < 32; c++)
            for (int i = t; i < HW; i += 16384)
                out_mbi[(size_t)(b * 32 + c) * HW + i] = 0.0f;
    }
}

// ---------------- merged front: w1/w2 split + input transpose + pnp(init) ----
__global__ __launch_bounds__(256) void k_front(const float* __restrict__ x,
                                               const float* __restrict__ w1,
                                               const float* __restrict__ w2,
                                               const float* __restrict__ wh,
                                               const int* __restrict__ ct_ind,
                                               const int* __restrict__ ct_img,
                                               const int* __restrict__ ct_num,
                                               float* __restrict__ out_mbi) {
    int bid = blockIdx.x;
    if (bid < 640) {
        int i = bid * 256 + threadIdx.x;
        if (i < 147456) {
            int oc = i / 576, k = i - oc * 576;
            int tap = k >> 6, ic = k & 63;
            split_store(&g_w1h[i], &g_w1l[i], w1[(oc * 64 + ic) * 9 + tap]);
        } else {
            int j = i - 147456;
            split_store(&g_w2h[j], &g_w2l[j], w2[j]);
        }
        return;
    }
    if (bid < 9856) {
        __shared__ float t[32][33];
        int xb = bid - 640;
        int pxb = xb % 1152;
        int cy = (xb / 1152) & 1;
        int b = xb / 2304;
        int c0 = cy * 32;
        int p0 = pxb * 32;
        int tx = threadIdx.x & 31, ty = threadIdx.x >> 5;
#pragma unroll
        for (int i = 0; i < 32; i += 8)
            t[ty + i][tx] = x[((size_t)b * CIN + c0 + ty + i) * HW + p0 + tx];
        __syncthreads();
#pragma unroll
        for (int i = 0; i < 32; i += 8) {
            size_t o = ((size_t)b * HW + p0 + ty + i) * CIN + c0 + tx;
            split_store(&g_xh_h[o], &g_xh_l[o], t[tx][ty + i]);
        }
        return;
    }
    int j = bid - 9856;
    pnp_body(j % 64, j / 64, 0, wh, ct_ind, ct_img, ct_num, out_mbi);
}

// ---------------- pnp(coarse) ----------------
__global__ __launch_bounds__(256) void k_pnp_c(const int* __restrict__ ct_num,
                                               float* __restrict__ out_mbc) {
    pnp_body(blockIdx.y, blockIdx.x, 1, nullptr, nullptr, nullptr, ct_num, out_mbc);
}

// ---------------- fused conv1 + conv2 (+featmul) ----------------
__global__ __launch_bounds__(512, 1) void k_conv(const float* __restrict__ b1,
                                                 const float* __restrict__ b2) {
    extern __shared__ char sm[];
    uint32_t sb = smem_u32(sm);
    int tid = threadIdx.x, lane = tid & 31, wid = tid >> 5;
    int b = blockIdx.y;
    int px0 = (blockIdx.x % 6) * 32;
    int py0 = (blockIdx.x / 6) * 4;
    int wm = wid & 1, wn = wid >> 1;

    float acc[4][4][4];
#pragma unroll
    for (int i = 0; i < 4; i++)
#pragma unroll
        for (int j = 0; j < 4; j++)
#pragma unroll
            for (int k = 0; k < 4; k++) acc[i][j][k] = 0.0f;

    size_t xbase = (size_t)b * HW;

    int ry[4], rx[4], sbs[4];
#pragma unroll
    for (int mt = 0; mt < 4; mt++) {
        int r = wm * 64 + mt * 16 + (lane & 15);
        int pr = r >> 5, pc = r & 31;
        ry[mt] = py0 + pr;
        rx[mt] = px0 + pc;
        sbs[mt] = (pr + 1) * SLAB_W + pc + 1;
    }

    int brow = tid >> 1;
    int bq0 = (tid & 1) * 2;
    const __half* w1h_p = g_w1h + (size_t)brow * 576 + bq0 * 8;
    const __half* w1l_p = g_w1l + (size_t)brow * 576 + bq0 * 8;
    uint32_t bd0 = swz64(brow, bq0 * 16);
    uint32_t bd1 = swz64(brow, bq0 * 16 + 16);

    auto load_b = [&](int chunk) {
        uint32_t st = sb + B_OFF + (uint32_t)(chunk % 3) * B_STAGE;
        int tap = chunk >> 1, half = chunk & 1;
        int wo = tap * 64 + half * 32;
        cp16(st + bd0, w1h_p + wo, 16);
        cp16(st + bd1, w1h_p + wo + 8, 16);
        cp16(st + 16384u + bd0, w1l_p + wo, 16);
        cp16(st + 16384u + bd1, w1l_p + wo + 8, 16);
    };

    for (int i = tid; i < 205 * 8; i += 512) {
        int s = i >> 3, q = i & 7;
        uint32_t d = swz128(s, q * 16);
        int sz = 0;
        size_t np = 0;
        if (s < SLAB_PX) {
            int sy = s / SLAB_W, sx = s - sy * SLAB_W;
            int yy = py0 - 1 + sy, xx = px0 - 1 + sx;
            if ((unsigned)yy < 192u && (unsigned)xx < 192u) {
                np = (xbase + yy * 192 + xx) * 64 + q * 8;
                sz = 16;
            }
        }
        cp16(sb + d, g_xh_h + np, sz);
        cp16(sb + SLAB_BYTES + d, g_xh_l + np, sz);
    }
    load_b(0); CP_COMMIT();
    load_b(1); CP_COMMIT();

    for (int c = 0; c < 18; c++) {
        CP_WAIT1();
        __syncthreads();
        if (c + 2 < 18) load_b(c + 2);
        CP_COMMIT();

        int tap = c >> 1, half = c & 1;
        int dy = tap / 3 - 1, dx = tap % 3 - 1;
        uint32_t sa[4];
#pragma unroll
        for (int mt = 0; mt < 4; mt++) {
            bool v = ((unsigned)(ry[mt] + dy) < 192u) && ((unsigned)(rx[mt] + dx) < 192u);
            sa[mt] = v ? (uint32_t)(sbs[mt] + dy * SLAB_W + dx) : (uint32_t)SLAB_ZERO;
        }
        uint32_t bst = sb + B_OFF + (uint32_t)(c % 3) * B_STAGE;
#pragma unroll
        for (int k16 = 0; k16 < 2; k16++) {
            int kb = k16 * 32;
            int acolb = half * 64 + kb + (lane >> 4) * 16;
            int brr = wn * 32 + ((lane >> 4) << 3) + (lane & 7);
            int bcolb = kb + ((lane >> 3) & 1) * 16;
            uint32_t bd_a = swz64(brr, bcolb);
            uint32_t bd_b = swz64(brr + 16, bcolb);

            uint32_t bh[4][2], bl[4][2];
            {
                uint32_t r[4];
                ldmx4(bst + bd_a, r);
                bh[0][0] = r[0]; bh[0][1] = r[1]; bh[1][0] = r[2]; bh[1][1] = r[3];
                ldmx4(bst + bd_b, r);
                bh[2][0] = r[0]; bh[2][1] = r[1]; bh[3][0] = r[2]; bh[3][1] = r[3];
                ldmx4(bst + 16384u + bd_a, r);
                bl[0][0] = r[0]; bl[0][1] = r[1]; bl[1][0] = r[2]; bl[1][1] = r[3];
                ldmx4(bst + 16384u + bd_b, r);
                bl[2][0] = r[0]; bl[2][1] = r[1]; bl[3][0] = r[2]; bl[3][1] = r[3];
            }
#pragma unroll
            for (int mt = 0; mt < 4; mt++) {
                uint32_t ah[4], al[4];
                uint32_t ad = swz128((int)sa[mt], acolb);
                ldmx4(sb + ad, ah);
                ldmx4(sb + SLAB_BYTES + ad, al);
#pragma unroll
                for (int nt = 0; nt < 4; nt++) hmma(acc[mt][nt], ah, bh[nt]);
#pragma unroll
                for (int nt = 0; nt < 4; nt++) hmma(acc[mt][nt], al, bh[nt]);
#pragma unroll
                for (int nt = 0; nt < 4; nt++) hmma(acc[mt][nt], ah, bl[nt]);
            }
        }
    }

    // ---------------- conv2 (4 x 64-oc phases), w2 preloaded once ----------------
    int wm2 = wid & 3, wn2 = wid >> 2;
    float acc2[2][2][4];
#pragma unroll
    for (int i = 0; i < 2; i++)
#pragma unroll
        for (int j = 0; j < 2; j++)
#pragma unroll
            for (int k = 0; k < 4; k++) acc2[i][j][k] = 0.0f;

    int w2row = tid >> 3, w2sg = tid & 7;
    uint32_t w2d = swz128(w2row, w2sg * 16);

    __syncthreads();
#pragma unroll
    for (int ph = 0; ph < 4; ph++) {
        cp16(sb + B_OFF + (uint32_t)ph * 16384u + w2d,
             g_w2h + (size_t)w2row * 256 + ph * 64 + w2sg * 8, 16);
        cp16(sb + B_OFF + (uint32_t)ph * 16384u + 8192u + w2d,
             g_w2l + (size_t)w2row * 256 + ph * 64 + w2sg * 8, 16);
    }
    CP_COMMIT();

    for (int ph = 0; ph < 4; ph++) {
        if (ph) __syncthreads();
        if ((wn >> 1) == ph) {
            int ocbase = (wn & 1) * 32;
#pragma unroll
            for (int mt = 0; mt < 4; mt++) {
#pragma unroll
                for (int nt = 0; nt < 4; nt++) {
                    int oc_l = ocbase + nt * 8 + (lane & 3) * 2;
                    float bb0 = __ldg(&b1[ph * 64 + oc_l]);
                    float bb1 = __ldg(&b1[ph * 64 + oc_l + 1]);
#pragma unroll
                    for (int rh = 0; rh < 2; rh++) {
                        int row = wm * 64 + mt * 16 + (lane >> 2) + rh * 8;
                        float t0 = fmaxf(acc[mt][nt][rh * 2 + 0] + bb0, 0.0f);
                        float t1 = fmaxf(acc[mt][nt][rh * 2 + 1] + bb1, 0.0f);
                        __half h0 = __float2half_rn(t0), h1 = __float2half_rn(t1);
                        uint32_t ad = (uint32_t)(row * 128 + ((oc_l * 2) ^ ((row & 7) << 4)));
                        *(__half2*)(sm + ad) = __halves2half2(h0, h1);
                        *(__half2*)(sm + 16384 + ad) = __halves2half2(
                            __float2half_rn(t0 - __half2float(h0)),
                            __float2half_rn(t1 - __half2float(h1)));
                    }
                }
            }
        }
        if (ph == 0) CP_WAIT0();
        __syncthreads();
        uint32_t wbase = sb + B_OFF + (uint32_t)ph * 16384u;
#pragma unroll
        for (int kc = 0; kc < 2; kc++) {
#pragma unroll
            for (int k16 = 0; k16 < 2; k16++) {
                int kcb = kc * 64 + k16 * 32;
                uint32_t bf2h[2][2], bf2l[2][2];
                int brow2 = wn2 * 16 + ((lane >> 4) << 3) + (lane & 7);
                int bcolb2 = kcb + ((lane >> 3) & 1) * 16;
                uint32_t bd2 = swz128(brow2, bcolb2);
                {
                    uint32_t r[4];
                    ldmx4(wbase + bd2, r);
                    bf2h[0][0] = r[0]; bf2h[0][1] = r[1]; bf2h[1][0] = r[2]; bf2h[1][1] = r[3];
                    ldmx4(wbase + 8192u + bd2, r);
                    bf2l[0][0] = r[0]; bf2l[0][1] = r[1]; bf2l[1][0] = r[2]; bf2l[1][1] = r[3];
                }
#pragma unroll
                for (int mt = 0; mt < 2; mt++) {
                    uint32_t ah[4], al[4];
                    int row = wm2 * 32 + mt * 16 + (lane & 15);
                    int colb = kcb + (lane >> 4) * 16;
                    uint32_t ad = swz128(row, colb);
                    ldmx4(sb + ad, ah);
                    ldmx4(sb + 16384u + ad, al);
#pragma unroll
                    for (int nt = 0; nt < 2; nt++) hmma(acc2[mt][nt], ah, bf2h[nt]);
#pragma unroll
                    for (int nt = 0; nt < 2; nt++) hmma(acc2[mt][nt], al, bf2h[nt]);
#pragma unroll
                    for (int nt = 0; nt < 2; nt++) hmma(acc2[mt][nt], ah, bf2l[nt]);
                }
            }
        }
    }

    // epilogue: feat = relu((D2 + b2) * (1 + union_init))
#pragma unroll
    for (int mt = 0; mt < 2; mt++) {
#pragma unroll
        for (int nt = 0; nt < 2; nt++) {
            int oc2 = wn2 * 16 + nt * 8 + (lane & 3) * 2;
            float bb0 = __ldg(&b2[oc2]), bb1 = __ldg(&b2[oc2 + 1]);
#pragma unroll
            for (int rh = 0; rh < 2; rh++) {
                int m = wm2 * 32 + mt * 16 + (lane >> 2) + rh * 8;
                int px = (py0 + (m >> 5)) * 192 + px0 + (m & 31);
                float u = g_union[b * HW + px];
                float s = 1.0f + u;
                float2 v;
                v.x = fmaxf((acc2[mt][nt][rh * 2 + 0] + bb0) * s, 0.0f);
                v.y = fmaxf((acc2[mt][nt][rh * 2 + 1] + bb1) * s, 0.0f);
                *(float2*)&g_feat[((size_t)b * HW + px) * 64 + oc2] = v;
            }
        }
    }
}

// ---------------- final: featmul pass 2 + NHWC -> NCHW ----------------
__global__ void k_final(float* __restrict__ out) {
    __shared__ float t[32][33];
    int b = blockIdx.z;
    int c0 = blockIdx.y * 32;
    int p0 = blockIdx.x * 32;
    int tx = threadIdx.x, ty = threadIdx.y;
#pragma unroll
    for (int i = 0; i < 32; i += 8) {
        int p = p0 + ty + i;
        float u = g_union[b * HW + p];
        float v = g_feat[((size_t)b * HW + p) * CIN + c0 + tx];
        t[ty + i][tx] = fmaxf(v * (1.0f + u), 0.0f);
    }
    __syncthreads();
#pragma unroll
    for (int i = 0; i < 32; i += 8)
        out[((size_t)b * CIN + c0 + ty + i) * HW + p0 + tx] = t[tx][ty + i];
}

// ---------------- bilinear sampling (NHWC), 2 CTAs per poly ----------------
__global__ __launch_bounds__(256) void k_sample(const int* __restrict__ ct_ind,
                                                const int* __restrict__ ct_img) {
    __shared__ float s_w[129][4];
    __shared__ int s_off[129][4];
    int n = blockIdx.x >> 1;
    int half = blockIdx.x & 1;
    int tid = threadIdx.x;
    int img = ct_img[n];
    if (tid < 129) {
        float ptx, pty;
        if (tid == 0) {
            int ind = ct_ind[n];
            ptx = (float)(ind % WW);
            pty = (float)(ind / WW);
        } else {
            ptx = g_init[(n * PPTS + tid - 1) * 2 + 0];
            pty = g_init[(n * PPTS + tid - 1) * 2 + 1];
        }
        float xs = ptx - 0.5f, ys = pty - 0.5f;
        float x0f = floorf(xs), y0f = floorf(ys);
        float wx = xs - x0f, wy = ys - y0f;
        int x0 = (int)x0f, y0 = (int)y0f;
#pragma unroll
        for (int k = 0; k < 4; k++) {
            int xi = x0 + (k & 1);
            int yi = y0 + (k >> 1);
            bool valid = (xi >= 0) && (xi < WW) && (yi >= 0) && (yi < HH);
            int xc = min(max(xi, 0), WW - 1);
            int yc = min(max(yi, 0), HH - 1);
            s_off[tid][k] = yc * WW + xc;
            float wxx = (k & 1) ? wx : (1.0f - wx);
            float wyy = (k >> 1) ? wy : (1.0f - wy);
            s_w[tid][k] = valid ? wxx * wyy : 0.0f;
        }
    }
    __syncthreads();
    const float* fb = g_feat + (size_t)img * HW * CIN;
    int beg = half * 4128, end = beg + 4128;
    for (int i = beg + tid; i < end; i += 256) {
        int pp = i >> 6;
        int c = i & 63;
        float v = s_w[pp][0] * fb[(size_t)s_off[pp][0] * CIN + c]
                + s_w[pp][1] * fb[(size_t)s_off[pp][1] * CIN + c]
                + s_w[pp][2] * fb[(size_t)s_off[pp][2] * CIN + c]
                + s_w[pp][3] * fb[(size_t)s_off[pp][3] * CIN + c];
        g_fp[(size_t)n * FPK + c * 129 + pp] = v;
    }
}

// ---------------- NT GEMMs for offsets (fp32, exact path) ----------------
template <int MODE>
__global__ __launch_bounds__(256) void k_gemm(const float* __restrict__ Bm,
                                              const float* __restrict__ bias,
                                              float* __restrict__ outc) {
    const int K = (MODE == 0) ? FPK : 512;
    const float* A = (MODE == 0) ? (const float*)g_fp : (const float*)g_tmp;
    __shared__ float sA[16][68];
    __shared__ float sB[16][68];
    int m0 = blockIdx.y * 64, n0 = blockIdx.x * 64;
    int tid = threadIdx.x;
    int tx = tid & 15, ty = tid >> 4;
    int kk = tid & 15, rr = tid >> 4;
    float acc[4][4];
#pragma unroll
    for (int i = 0; i < 4; i++)
#pragma unroll
        for (int j = 0; j < 4; j++) acc[i][j] = 0.0f;

    int kbeg = (MODE == 0) ? blockIdx.z * 688 : 0;
    int kend = (MODE == 0) ? kbeg + 688 : 512;
    for (int k0 = kbeg; k0 < kend; k0 += 16) {
        __syncthreads();
#pragma unroll
        for (int pass = 0; pass < 4; pass++) {
            int row = rr + pass * 16;
            sA[kk][row] = A[(size_t)(m0 + row) * K + k0 + kk];
            sB[kk][row] = Bm[(size_t)(n0 + row) * K + k0 + kk];
        }
        __syncthreads();
#pragma unroll
        for (int k2 = 0; k2 < 16; k2++) {
            float4 a4 = *(const float4*)&sA[k2][ty * 4];
            float4 b4 = *(const float4*)&sB[k2][tx * 4];
            acc[0][0] += a4.x * b4.x; acc[0][1] += a4.x * b4.y; acc[0][2] += a4.x * b4.z; acc[0][3] += a4.x * b4.w;
            acc[1][0] += a4.y * b4.x; acc[1][1] += a4.y * b4.y; acc[1][2] += a4.y * b4.z; acc[1][3] += a4.y * b4.w;
            acc[2][0] += a4.z * b4.x; acc[2][1] += a4.z * b4.y; acc[2][2] += a4.z * b4.z; acc[2][3] += a4.z * b4.w;
            acc[3][0] += a4.w * b4.x; acc[3][1] += a4.w * b4.y; acc[3][2] += a4.w * b4.z; acc[3][3] += a4.w * b4.w;
        }
    }
    if (MODE == 0) {
#pragma unroll
        for (int i = 0; i < 4; i++)
#pragma unroll
            for (int j = 0; j < 4; j++)
                g_part[((size_t)blockIdx.z * 128 + m0 + ty * 4 + i) * 512 + n0 + tx * 4 + j] = acc[i][j];
    } else {
#pragma unroll
        for (int i = 0; i < 4; i++) {
            int m = m0 + ty * 4 + i;
#pragma unroll
            for (int j = 0; j < 4; j++) {
                int nn = n0 + tx * 4 + j;
                float v = acc[i][j] + bias[nn];
                float cr = v * 4.0f + g_init[m * 256 + nn];
                g_coarse[m * 256 + nn] = cr;
                outc[m * 256 + nn] = cr * 4.0f;
            }
        }
    }
}

// ---------------- reduce (12 partials) + coarse-side zeroing ----------------
__global__ void k_reduce(const int* __restrict__ ct_num, float* __restrict__ mbc) {
    int bid = blockIdx.x;
    if (bid < 256) {
        int i = bid * 256 + threadIdx.x;
        float s = 0.0f;
#pragma unroll
        for (int p = 0; p < NSPLIT; p++) s += g_part[(size_t)p * 65536 + i];
        g_tmp[i] = s;
        return;
    }
    int i = (bid - 256) * 256 + threadIdx.x;    // < 147456
    ((unsigned*)g_union)[i] = 0u;
    int b = i / HW, px = i - b * HW;
    int cn = ct_num[b];
    for (int c = cn; c < 32; c++)
        mbc[(size_t)(b * 32 + c) * HW + px] = 0.0f;
}

// ---------------- launcher ----------------
extern "C" void kernel_launch(void* const* d_in, const int* in_sizes, int n_in,
                              void* d_out, int out_size) {
    const float* wh     = (const float*)d_in[0];
    const float* cnn    = (const float*)d_in[1];
    const float* w1     = (const float*)d_in[2];
    const float* b1     = (const float*)d_in[3];
    const float* w2     = (const float*)d_in[4];
    const float* b2     = (const float*)d_in[5];
    const float* wpoly  = (const float*)d_in[6];
    const float* wfuse  = (const float*)d_in[7];
    const float* bfuse  = (const float*)d_in[8];
    const int*   ct_ind = (const int*)d_in[9];
    const int*   ct_img = (const int*)d_in[10];
    const int*   ct_num = (const int*)d_in[11];

    float* out        = (float*)d_out;
    float* out_init   = out + O_INIT;
    float* out_coarse = out + O_COARSE;
    float* out_mbi    = out + O_MBI;
    float* out_mbc    = out + O_MBC;
    float* out_feat   = out + O_FEAT;

    cudaFuncSetAttribute(k_conv, cudaFuncAttributeMaxDynamicSharedMemorySize, CONV_SMEM);

    k_init<<<128, 128>>>(wh, ct_ind, ct_img, out_init, ct_num, out_mbi);        // 0
    k_front<<<11392, 256>>>(cnn, w1, w2, wh, ct_ind, ct_img, ct_num, out_mbi);  // 1
    k_conv<<<dim3(288, 4), 512, CONV_SMEM>>>(b1, b2);                           // 2
    k_sample<<<256, 256>>>(ct_ind, ct_img);                                     // 3

    k_gemm<0><<<dim3(8, 2, NSPLIT), 256>>>(wpoly, nullptr, nullptr);
    k_reduce<<<832, 256>>>(ct_num, out_mbc);
    k_gemm<1><<<dim3(4, 2), 256>>>(wfuse, bfuse, out_coarse);

    k_pnp_c<<<dim3(24, 64), 256>>>(ct_num, out_mbc);
    k_final<<<dim3(1152, 2, 4), dim3(32, 8)>>>(out_feat);
}